// round 2
// baseline (speedup 1.0000x reference)
#include <cuda_runtime.h>
#include <math.h>

// Problem shape (fixed by the reference)
#define BB 64
#define SS 2048
#define DD 256
#define NSPLIT 32
#define CHUNK (SS / NSPLIT)   // 64 rows of S per CTA

// Scratch for partial reductions (static — no dynamic allocation allowed)
__device__ float g_psum[BB * NSPLIT * DD];
__device__ float g_pmax[BB * NSPLIT * DD];
__device__ float g_pcnt[BB * NSPLIT];
__device__ int   g_arrived[BB];   // zero-initialized; reset to 0 by last CTA each call

__device__ __forceinline__ float neg_inf() { return __int_as_float(0xff800000); }

// Fused kernel: each CTA reduces CHUNK rows of S for one (b, split), writes
// partials, then the LAST CTA to finish for each b combines the partials and
// writes the final [max | mean] row. Single launch, no second kernel.
// Block = 256 threads: d4 = tid % 64 (float4 lane over D=256), sg = tid / 64.
__global__ __launch_bounds__(256) void pool_fused(const float* __restrict__ feats,
                                                  const float* __restrict__ mask,
                                                  float* __restrict__ out) {
    const int split = blockIdx.x;
    const int b     = blockIdx.y;
    const int tid   = threadIdx.x;
    const int d4    = tid & 63;
    const int sg    = tid >> 6;

    const float4* __restrict__ frow =
        reinterpret_cast<const float4*>(feats + (size_t)b * SS * DD);
    const float* __restrict__ mrow = mask + (size_t)b * SS;

    float4 sum = make_float4(0.f, 0.f, 0.f, 0.f);
    float4 mx  = make_float4(neg_inf(), neg_inf(), neg_inf(), neg_inf());
    float  cnt = 0.f;

    const int s0 = split * CHUNK;
#pragma unroll 8
    for (int i = 0; i < CHUNK / 4; ++i) {
        const int s = s0 + sg + 4 * i;
        float  m = mrow[s];
        float4 f = frow[(size_t)s * 64 + d4];
        bool   v = (m > 0.f);
        cnt += m;
        sum.x += f.x * m;  sum.y += f.y * m;
        sum.z += f.z * m;  sum.w += f.w * m;
        mx.x = fmaxf(mx.x, v ? f.x : neg_inf());
        mx.y = fmaxf(mx.y, v ? f.y : neg_inf());
        mx.z = fmaxf(mx.z, v ? f.z : neg_inf());
        mx.w = fmaxf(mx.w, v ? f.w : neg_inf());
    }

    // CTA-level reduce: 256 -> 64 lanes (one float4 per d4 lane)
    __shared__ float4 s_sum[256];
    __shared__ float4 s_max[256];
    __shared__ float  s_cnt[4];
    s_sum[tid] = sum;
    s_max[tid] = mx;
    if (d4 == 0) s_cnt[sg] = cnt;
    __syncthreads();

    if (tid < 64) {
        float4 a = s_sum[tid];
        float4 m = s_max[tid];
#pragma unroll
        for (int k = 1; k < 4; ++k) {
            float4 a2 = s_sum[tid + 64 * k];
            float4 m2 = s_max[tid + 64 * k];
            a.x += a2.x; a.y += a2.y; a.z += a2.z; a.w += a2.w;
            m.x = fmaxf(m.x, m2.x); m.y = fmaxf(m.y, m2.y);
            m.z = fmaxf(m.z, m2.z); m.w = fmaxf(m.w, m2.w);
        }
        const size_t base = ((size_t)b * NSPLIT + split) * DD;
        reinterpret_cast<float4*>(g_psum + base)[tid] = a;
        reinterpret_cast<float4*>(g_pmax + base)[tid] = m;
        if (tid == 0)
            g_pcnt[b * NSPLIT + split] = s_cnt[0] + s_cnt[1] + s_cnt[2] + s_cnt[3];
    }

    // Make partials visible, then count arrival (threadfence-reduction pattern)
    __threadfence();
    __syncthreads();
    __shared__ int s_last;
    if (tid == 0) {
        int prev = atomicAdd(&g_arrived[b], 1);
        s_last = (prev == NSPLIT - 1);
    }
    __syncthreads();
    if (!s_last) return;

    // Last CTA for this b: combine NSPLIT partials. Thread tid owns column d=tid.
    {
        const int d = tid;  // 0..255
        float fsum = 0.f;
        float fmx  = neg_inf();
        float fcnt = 0.f;
#pragma unroll
        for (int sp = 0; sp < NSPLIT; ++sp) {
            const size_t base = ((size_t)b * NSPLIT + sp) * DD;
            fsum += g_psum[base + d];
            fmx   = fmaxf(fmx, g_pmax[base + d]);
            fcnt += g_pcnt[b * NSPLIT + sp];
        }
        out[(size_t)b * (2 * DD) + d]      = fmx;
        out[(size_t)b * (2 * DD) + DD + d] = fsum / fcnt;
        if (tid == 0) g_arrived[b] = 0;   // reset for next graph replay
    }
}

extern "C" void kernel_launch(void* const* d_in, const int* in_sizes, int n_in,
                              void* d_out, int out_size) {
    const float* feats = (const float*)d_in[0];
    const float* mask  = (const float*)d_in[1];
    float* out = (float*)d_out;

    dim3 grid(NSPLIT, BB);
    pool_fused<<<grid, 256>>>(feats, mask, out);
}

// round 3
// speedup vs baseline: 1.3600x; 1.3600x over previous
#include <cuda_runtime.h>

// Problem shape (fixed by the reference)
#define BB 64
#define SS 2048
#define DD 256
#define NSPLIT 16
#define CHUNK (SS / NSPLIT)   // 128 rows of S per CTA
#define BATCH 8               // explicit in-flight float4 loads per thread

// Accumulators in global scratch (statically zero-initialized; reset by finalizer
// after every use so graph replays see a clean state).
__device__ float    g_sum [BB * DD];
__device__ unsigned g_maxo[BB * DD];   // order-preserving uint encoding; 0 == "-inf"
__device__ float    g_cnt [BB];
__device__ int      g_arrived[BB];

__device__ __forceinline__ float neg_inf() { return __int_as_float(0xff800000); }

// Monotone float <-> uint mapping so atomicMax(unsigned) == float max.
__device__ __forceinline__ unsigned f2o(float f) {
    unsigned u = __float_as_uint(f);
    return (u & 0x80000000u) ? ~u : (u | 0x80000000u);
}
__device__ __forceinline__ float o2f(unsigned u) {
    return __uint_as_float((u & 0x80000000u) ? (u & 0x7fffffffu) : ~u);
}

// One CTA per (split, b). 256 threads: d4 = tid % 64 (float4 lane over D=256),
// sg = tid / 64 (4 s-rows in parallel). Explicitly batched loads guarantee
// MLP_p1 = 8 LDG.128 (+8 uniform mask LDG.32) in flight per thread.
__global__ void __launch_bounds__(256, 4)
pool_fused(const float* __restrict__ feats,
           const float* __restrict__ mask,
           float* __restrict__ out) {
    const int split = blockIdx.x;
    const int b     = blockIdx.y;
    const int tid   = threadIdx.x;
    const int d4    = tid & 63;
    const int sg    = tid >> 6;

    const int s0 = split * CHUNK;
    const float4* __restrict__ p =
        reinterpret_cast<const float4*>(feats) + ((size_t)b * SS + s0 + sg) * 64 + d4;
    const float* __restrict__ mp = mask + (size_t)b * SS + s0 + sg;

    float4 sum = make_float4(0.f, 0.f, 0.f, 0.f);
    float4 mx  = make_float4(neg_inf(), neg_inf(), neg_inf(), neg_inf());
    float  cnt = 0.f;

#pragma unroll
    for (int batch = 0; batch < CHUNK / (4 * BATCH); ++batch) {   // 4 outer iters
        float  mbuf[BATCH];
        float4 fbuf[BATCH];
#pragma unroll
        for (int j = 0; j < BATCH; ++j) mbuf[j] = mp[j * 4];
#pragma unroll
        for (int j = 0; j < BATCH; ++j) fbuf[j] = p[j * 4 * 64];
#pragma unroll
        for (int j = 0; j < BATCH; ++j) {
            const float  m = mbuf[j];
            const float4 f = fbuf[j];
            const bool   v = (m > 0.f);
            cnt += m;
            sum.x += f.x * m;  sum.y += f.y * m;
            sum.z += f.z * m;  sum.w += f.w * m;
            mx.x = fmaxf(mx.x, v ? f.x : neg_inf());
            mx.y = fmaxf(mx.y, v ? f.y : neg_inf());
            mx.z = fmaxf(mx.z, v ? f.z : neg_inf());
            mx.w = fmaxf(mx.w, v ? f.w : neg_inf());
        }
        mp += 4 * BATCH;
        p  += 4 * BATCH * 64;
    }

    // CTA-level reduce: 4 sg-groups -> 1 (64 float4 lanes remain)
    __shared__ float4 s_sum[256];
    __shared__ float4 s_max[256];
    __shared__ float  s_cnt[4];
    s_sum[tid] = sum;
    s_max[tid] = mx;
    if (d4 == 0) s_cnt[sg] = cnt;
    __syncthreads();

    if (tid < 64) {
        float4 a = s_sum[tid];
        float4 m = s_max[tid];
#pragma unroll
        for (int k = 1; k < 4; ++k) {
            float4 a2 = s_sum[tid + 64 * k];
            float4 m2 = s_max[tid + 64 * k];
            a.x += a2.x; a.y += a2.y; a.z += a2.z; a.w += a2.w;
            m.x = fmaxf(m.x, m2.x); m.y = fmaxf(m.y, m2.y);
            m.z = fmaxf(m.z, m2.z); m.w = fmaxf(m.w, m2.w);
        }
        // Fire-and-forget reductions into per-(b,d) accumulators (REDG, no return)
        const int dbase = b * DD + tid * 4;
        atomicAdd(&g_sum[dbase + 0], a.x);
        atomicAdd(&g_sum[dbase + 1], a.y);
        atomicAdd(&g_sum[dbase + 2], a.z);
        atomicAdd(&g_sum[dbase + 3], a.w);
        atomicMax(&g_maxo[dbase + 0], f2o(m.x));
        atomicMax(&g_maxo[dbase + 1], f2o(m.y));
        atomicMax(&g_maxo[dbase + 2], f2o(m.z));
        atomicMax(&g_maxo[dbase + 3], f2o(m.w));
        if (tid == 0)
            atomicAdd(&g_cnt[b], s_cnt[0] + s_cnt[1] + s_cnt[2] + s_cnt[3]);
    }

    // Threadfence-reduction pattern: order our REDGs before the arrival counter.
    __threadfence();
    __syncthreads();
    __shared__ int s_last;
    if (tid == 0) {
        int prev = atomicAdd(&g_arrived[b], 1);
        s_last = (prev == NSPLIT - 1);
    }
    __syncthreads();
    if (!s_last) return;

    // Last CTA for this b: accumulators are final. Read L2-coherent (.cg),
    // write output, and reset scratch for the next graph replay.
    {
        const int d = tid;  // 0..255
        float    fsum = __ldcg(&g_sum[b * DD + d]);
        unsigned mo   = __ldcg(&g_maxo[b * DD + d]);
        float    fcnt = __ldcg(&g_cnt[b]);
        out[(size_t)b * (2 * DD) + d]      = o2f(mo);
        out[(size_t)b * (2 * DD) + DD + d] = fsum / fcnt;
        __stcg(&g_sum[b * DD + d], 0.f);
        __stcg(&g_maxo[b * DD + d], 0u);
        if (tid == 0) {
            __stcg(&g_cnt[b], 0.f);
            __stcg(&g_arrived[b], 0);
        }
    }
}

extern "C" void kernel_launch(void* const* d_in, const int* in_sizes, int n_in,
                              void* d_out, int out_size) {
    const float* feats = (const float*)d_in[0];
    const float* mask  = (const float*)d_in[1];
    float* out = (float*)d_out;

    dim3 grid(NSPLIT, BB);
    pool_fused<<<grid, 256>>>(feats, mask, out);
}